// round 16
// baseline (speedup 1.0000x reference)
#include <cuda_runtime.h>
#include <cuda_bf16.h>
#include <math.h>
#include <stdint.h>

#define B_ 8
#define N_ 729
#define C_ 1152
#define H_ 16
#define D_ 72
#define F_ 4304
#define R_ 23
#define NA 365
#define NB 364
#define NM 706
#define NU 342
#define NP 736
#define NPV 736
#define EPSLN 1e-6f
#define SCALE_ 0.1178511301977579f

// ------------------------- scratch (static device globals) -------------------
__device__ float  g_xln[B_*N_*C_];
__device__ float  g_v  [B_*N_*C_];
__device__ float  g_h  [B_*N_*C_];
__device__ __align__(16) float g_sc[(size_t)B_*H_*N_*NP];
__device__ float2 g_wk2[C_*D_];
__device__ double g_mnP[3*B_*N_*D_];
__device__ double g_mnD[B_*N_*D_];
__device__ double g_nmax[B_*NA];
__device__ int    g_nidx[B_*NA];
__device__ int    g_edge[B_*NA];
__device__ float  g_mg [B_*NM*C_];
__device__ float  g_bqkv[3*C_];
// bf16 split activations
__device__ __align__(16) __nv_bfloat16 g_xh [B_*N_*C_];
__device__ __align__(16) __nv_bfloat16 g_xl [B_*N_*C_];
__device__ __align__(16) __nv_bfloat16 g_qh [B_*N_*C_];
__device__ __align__(16) __nv_bfloat16 g_ql [B_*N_*C_];
__device__ __align__(16) __nv_bfloat16 g_kh [B_*N_*C_];
__device__ __align__(16) __nv_bfloat16 g_kl [B_*N_*C_];
__device__ __align__(16) __nv_bfloat16 g_ph [(size_t)B_*H_*N_*NP];
__device__ __align__(16) __nv_bfloat16 g_pl [(size_t)B_*H_*N_*NP];
__device__ __align__(16) __nv_bfloat16 g_vth[B_*H_*D_*NPV];
__device__ __align__(16) __nv_bfloat16 g_vtl[B_*H_*D_*NPV];
__device__ __align__(16) __nv_bfloat16 g_aoh[B_*N_*C_];
__device__ __align__(16) __nv_bfloat16 g_aol[B_*N_*C_];
__device__ __align__(16) __nv_bfloat16 g_h2h[B_*NM*C_];
__device__ __align__(16) __nv_bfloat16 g_h2l[B_*NM*C_];
__device__ __align__(16) __nv_bfloat16 g_f1h[B_*NM*F_];
__device__ __align__(16) __nv_bfloat16 g_f1l[B_*NM*F_];
// bf16 split transposed weights [N][K]
__device__ __align__(16) __nv_bfloat16 g_wqkvth[3*C_*C_];
__device__ __align__(16) __nv_bfloat16 g_wqkvtl[3*C_*C_];
__device__ __align__(16) __nv_bfloat16 g_woth[C_*C_];
__device__ __align__(16) __nv_bfloat16 g_wotl[C_*C_];
__device__ __align__(16) __nv_bfloat16 g_w1th[(size_t)F_*C_];
__device__ __align__(16) __nv_bfloat16 g_w1tl[(size_t)F_*C_];
__device__ __align__(16) __nv_bfloat16 g_w2th[(size_t)C_*F_];
__device__ __align__(16) __nv_bfloat16 g_w2tl[(size_t)C_*F_];

// --------------------------- asm helpers --------------------------------------
static __device__ __forceinline__ uint32_t smem_u32(const void* p) {
    uint32_t a;
    asm("{ .reg .u64 t; cvta.to.shared.u64 t, %1; cvt.u32.u64 %0, t; }" : "=r"(a) : "l"(p));
    return a;
}
static __device__ __forceinline__ void ldsm_x4(uint32_t addr, uint32_t* r) {
    asm volatile("ldmatrix.sync.aligned.m8n8.x4.shared.b16 {%0,%1,%2,%3}, [%4];"
        : "=r"(r[0]), "=r"(r[1]), "=r"(r[2]), "=r"(r[3]) : "r"(addr));
}
static __device__ __forceinline__ void mma_bf16(float* d, const uint32_t* a, const uint32_t* b) {
    asm volatile("mma.sync.aligned.m16n8k16.row.col.f32.bf16.bf16.f32 "
        "{%0,%1,%2,%3}, {%4,%5,%6,%7}, {%8,%9}, {%0,%1,%2,%3};"
        : "+f"(d[0]), "+f"(d[1]), "+f"(d[2]), "+f"(d[3])
        : "r"(a[0]), "r"(a[1]), "r"(a[2]), "r"(a[3]), "r"(b[0]), "r"(b[1]));
}
static __device__ __forceinline__ void cp_async16(uint32_t saddr, const void* gaddr, int sz) {
    asm volatile("cp.async.ca.shared.global [%0], [%1], 16, %2;"
        :: "r"(saddr), "l"(gaddr), "r"(sz) : "memory");
}
#define CP_COMMIT() asm volatile("cp.async.commit_group;" ::: "memory")
#define CP_WAIT2()  asm volatile("cp.async.wait_group 2;" ::: "memory")

static __device__ __forceinline__ void df_acc(float& hi, float& lo, float a, float bh, float bl)
{
    float p  = a * bh;
    float e  = fmaf(a, bh, -p);
    float t  = hi + p;
    float bb = t - hi;
    float err = (hi - (t - bb)) + (p - bb);
    hi = t;
    lo += err + e + a * bl;
}

__device__ __forceinline__ float gelu_tanh(float x)
{
    float x3 = x*x*x;
    float t = tanhf(0.7978845608028654f*(x + 0.044715f*x3));
    return 0.5f*x*(1.f + t);
}

// =================== shared MMA core: 128 thr, 4 warps, warp tile 64x64 ========
// smem tile: 128 rows x 64B (KC=32 halves), XOR-swizzled 16B chunks:
//   chunk' = (chunk + (row>>1)) & 3   -> conflict-free ldmatrix + cp.async
#define KC 32
#define TILE_B 8192              // 128*64
#define STAGE_B (4*TILE_B)       // 32768
#define STAGES 3
#define MM_SMEM (STAGES*STAGE_B) // 98304
#define MM_THREADS 128

static __device__ __forceinline__ uint32_t sw_off(int row, int c4) {
    return (uint32_t)(row*64 + (((c4 + (row >> 1)) & 3) << 4));
}

// warp decomposition: wm = wid&1 (M half), wn = wid>>1 (N half); warp tile 64x64
static __device__ __forceinline__ void mma_stage_compute(
    uint32_t smb, int s, int wm, int wn, int lane, float acc[4][8][4])
{
    uint32_t sa  = smb + s*STAGE_B;
    uint32_t aT  = sa;
    uint32_t alT = sa + TILE_B;
    uint32_t bhT = sa + 2*TILE_B;
    uint32_t blT = sa + 3*TILE_B;
    #pragma unroll
    for (int k16 = 0; k16 < 2; k16++) {
        uint32_t Ah2[4][4], Al2[4][4];
        #pragma unroll
        for (int mi = 0; mi < 4; mi++) {
            int rowl = wm*64 + mi*16 + (lane & 15);
            int c4 = k16*2 + (lane >> 4);
            uint32_t off = sw_off(rowl, c4);
            ldsm_x4(aT + off, Ah2[mi]);
            ldsm_x4(alT + off, Al2[mi]);
        }
        #pragma unroll
        for (int nj = 0; nj < 4; nj++) {
            int rowl = wn*64 + nj*16 + (lane & 7) + ((lane >> 4) * 8);
            int c4 = k16*2 + ((lane >> 3) & 1);
            uint32_t off = sw_off(rowl, c4);
            uint32_t bh[4], bl[4];
            ldsm_x4(bhT + off, bh);
            ldsm_x4(blT + off, bl);
            #pragma unroll
            for (int mi = 0; mi < 4; mi++) {
                mma_bf16(acc[mi][nj*2],   Ah2[mi], bh);
                mma_bf16(acc[mi][nj*2],   Ah2[mi], bl);
                mma_bf16(acc[mi][nj*2],   Al2[mi], bh);
                mma_bf16(acc[mi][nj*2+1], Ah2[mi], bh+2);
                mma_bf16(acc[mi][nj*2+1], Ah2[mi], bl+2);
                mma_bf16(acc[mi][nj*2+1], Al2[mi], bh+2);
            }
        }
    }
}

static __device__ __forceinline__ void mma_load_stage(
    uint32_t smb, int c, int tid,
    const __nv_bfloat16* const* srcs, const size_t* lds,
    const int* rbase, const int* rlim, int klim)
{
    int s = c % STAGES;
    int k0 = c * KC;
    #pragma unroll
    for (int t = 0; t < 4; t++) {
        #pragma unroll
        for (int it = 0; it < 4; it++) {          // 128 thr * 4 = 512 = 128 rows * 4 chunks
            int idx = tid + it*MM_THREADS;
            int row = idx >> 2, g = idx & 3;
            int grow = rbase[t] + row, gk = k0 + g*8;
            bool ok = (grow < rlim[t]) && (gk < klim);
            const void* gaddr = ok ? (const void*)(srcs[t] + (size_t)grow*lds[t] + gk)
                                   : (const void*)srcs[t];
            uint32_t saddr = smb + s*STAGE_B + t*TILE_B + sw_off(row, g);
            cp_async16(saddr, gaddr, ok ? 16 : 0);
        }
    }
    CP_COMMIT();
}

// 3-stage mainloop (requires nc >= 3, true for all call sites: min is qk nc=3)
#define MMA_MAINLOOP(NCVAR) \
    mma_load_stage(smb, 0, tid, srcs, lds, rbase, rlim, klim_); \
    if (NCVAR > 1) mma_load_stage(smb, 1, tid, srcs, lds, rbase, rlim, klim_); \
    for (int c = 0; c < NCVAR; c++) { \
        if (c+2 < NCVAR) mma_load_stage(smb, c+2, tid, srcs, lds, rbase, rlim, klim_); \
        else             CP_COMMIT(); \
        CP_WAIT2(); \
        __syncthreads(); \
        mma_stage_compute(smb, c % STAGES, wm, wn, lane, acc); \
        __syncthreads(); \
    }

// --------------------- general dense GEMM (weights) ----------------------------
__global__ __launch_bounds__(MM_THREADS,2) void mma_gemm(
    const __nv_bfloat16* __restrict__ Ah, const __nv_bfloat16* __restrict__ Al,
    const __nv_bfloat16* __restrict__ BTh, const __nv_bfloat16* __restrict__ BTl,
    const float* __restrict__ bias, const float* __restrict__ add,
    float* __restrict__ Cout,
    __nv_bfloat16* __restrict__ Oh, __nv_bfloat16* __restrict__ Ol,
    int M, int Nn, int K, int act)
{
    extern __shared__ __align__(16) char sm[];
    const int tid = threadIdx.x;
    const int wid = tid >> 5, lane = tid & 31;
    const int wm = wid & 1, wn = wid >> 1;
    const int n0 = blockIdx.x * 128, r0 = blockIdx.y * 128;
    const uint32_t smb = smem_u32(sm);

    const int nc = (K + KC - 1) / KC;
    const int klim_ = K;
    float acc[4][8][4] = {};

    const __nv_bfloat16* srcs[4] = {Ah, Al, BTh, BTl};
    const size_t lds[4] = {(size_t)K, (size_t)K, (size_t)K, (size_t)K};
    const int rbase[4] = {r0, r0, n0, n0};
    const int rlim[4]  = {M, M, Nn, Nn};

    MMA_MAINLOOP(nc)

    #pragma unroll
    for (int mi = 0; mi < 4; mi++) {
        int rA = r0 + wm*64 + mi*16 + (lane >> 2);
        #pragma unroll
        for (int ni = 0; ni < 8; ni++) {
            int cA = n0 + wn*64 + ni*8 + (lane & 3)*2;
            #pragma unroll
            for (int hrow = 0; hrow < 2; hrow++) {
                int r = rA + hrow*8;
                if (r >= M) continue;
                #pragma unroll
                for (int dc = 0; dc < 2; dc++) {
                    int cg = cA + dc;
                    if (cg >= Nn) continue;
                    float vv = acc[mi][ni][hrow*2 + dc] + (bias ? bias[cg] : 0.f);
                    if (act) vv = gelu_tanh(vv);
                    if (add) vv += add[(size_t)r*Nn + cg];
                    if (Cout) Cout[(size_t)r*Nn + cg] = vv;
                    if (Oh) {
                        __nv_bfloat16 hi = __float2bfloat16(vv);
                        Oh[(size_t)r*Nn + cg] = hi;
                        Ol[(size_t)r*Nn + cg] = __float2bfloat16(vv - __bfloat162float(hi));
                    }
                }
            }
        }
    }
}

// --------------------- fused QKV GEMM (Nn = 3*C) -------------------------------
__global__ __launch_bounds__(MM_THREADS,2) void mma_gemm_qkv(
    const __nv_bfloat16* __restrict__ Ah, const __nv_bfloat16* __restrict__ Al,
    const __nv_bfloat16* __restrict__ BTh, const __nv_bfloat16* __restrict__ BTl,
    const float* __restrict__ bias,
    __nv_bfloat16* __restrict__ qh, __nv_bfloat16* __restrict__ ql,
    __nv_bfloat16* __restrict__ kh, __nv_bfloat16* __restrict__ kl,
    float* __restrict__ v, int M)
{
    extern __shared__ __align__(16) char sm[];
    const int tid = threadIdx.x;
    const int wid = tid >> 5, lane = tid & 31;
    const int wm = wid & 1, wn = wid >> 1;
    const int n0 = blockIdx.x * 128, r0 = blockIdx.y * 128;
    const uint32_t smb = smem_u32(sm);
    const int K = C_, Nn = 3*C_;

    const int nc = (K + KC - 1) / KC;
    const int klim_ = K;
    float acc[4][8][4] = {};

    const __nv_bfloat16* srcs[4] = {Ah, Al, BTh, BTl};
    const size_t lds[4] = {(size_t)K, (size_t)K, (size_t)K, (size_t)K};
    const int rbase[4] = {r0, r0, n0, n0};
    const int rlim[4]  = {M, M, Nn, Nn};

    MMA_MAINLOOP(nc)

    #pragma unroll
    for (int mi = 0; mi < 4; mi++) {
        int rA = r0 + wm*64 + mi*16 + (lane >> 2);
        #pragma unroll
        for (int ni = 0; ni < 8; ni++) {
            int cA = n0 + wn*64 + ni*8 + (lane & 3)*2;
            #pragma unroll
            for (int hrow = 0; hrow < 2; hrow++) {
                int r = rA + hrow*8;
                if (r >= M) continue;
                #pragma unroll
                for (int dc = 0; dc < 2; dc++) {
                    int cg = cA + dc;
                    float vv = acc[mi][ni][hrow*2 + dc] + bias[cg];
                    if (cg < C_) {
                        __nv_bfloat16 hi = __float2bfloat16(vv);
                        qh[(size_t)r*C_ + cg] = hi;
                        ql[(size_t)r*C_ + cg] = __float2bfloat16(vv - __bfloat162float(hi));
                    } else if (cg < 2*C_) {
                        __nv_bfloat16 hi = __float2bfloat16(vv);
                        kh[(size_t)r*C_ + cg - C_] = hi;
                        kl[(size_t)r*C_ + cg - C_] = __float2bfloat16(vv - __bfloat162float(hi));
                    } else {
                        v[(size_t)r*C_ + cg - 2*C_] = vv;
                    }
                }
            }
        }
    }
}

// --------------------- attention: S = scale*Q@K^T + mask (MMA) ------------------
__global__ __launch_bounds__(MM_THREADS,2) void qk_mma(
    const __nv_bfloat16* __restrict__ qh, const __nv_bfloat16* __restrict__ ql,
    const __nv_bfloat16* __restrict__ kh, const __nv_bfloat16* __restrict__ kl,
    const float* __restrict__ mask, float* __restrict__ S)
{
    extern __shared__ __align__(16) char sm[];
    const int tid = threadIdx.x;
    const int wid = tid >> 5, lane = tid & 31;
    const int wm = wid & 1, wn = wid >> 1;
    const int bh = blockIdx.z, b = bh >> 4, h = bh & 15;
    const int n0 = blockIdx.x * 128, r0 = blockIdx.y * 128;
    const uint32_t smb = smem_u32(sm);
    const size_t hoff = (size_t)b*N_*C_ + h*D_;

    const int nc = (D_ + KC - 1) / KC;
    const int klim_ = D_;
    float acc[4][8][4] = {};

    const __nv_bfloat16* srcs[4] = {qh + hoff, ql + hoff, kh + hoff, kl + hoff};
    const size_t lds[4] = {C_, C_, C_, C_};
    const int rbase[4] = {r0, r0, n0, n0};
    const int rlim[4]  = {N_, N_, N_, N_};

    MMA_MAINLOOP(nc)

    #pragma unroll
    for (int mi = 0; mi < 4; mi++) {
        int rA = r0 + wm*64 + mi*16 + (lane >> 2);
        #pragma unroll
        for (int ni = 0; ni < 8; ni++) {
            int cA = n0 + wn*64 + ni*8 + (lane & 3)*2;
            #pragma unroll
            for (int hrow = 0; hrow < 2; hrow++) {
                int r = rA + hrow*8;
                if (r >= N_) continue;
                #pragma unroll
                for (int dc = 0; dc < 2; dc++) {
                    int cg = cA + dc;
                    if (cg >= N_) continue;
                    S[((size_t)bh*N_ + r)*NP + cg] =
                        acc[mi][ni][hrow*2 + dc]*SCALE_ + mask[((size_t)b*N_ + r)*N_ + cg];
                }
            }
        }
    }
}

// --------------------- attention: out = P @ V^T (MMA) ---------------------------
__global__ __launch_bounds__(MM_THREADS,2) void av_mma(
    const __nv_bfloat16* __restrict__ ph, const __nv_bfloat16* __restrict__ pl,
    const __nv_bfloat16* __restrict__ vth, const __nv_bfloat16* __restrict__ vtl,
    __nv_bfloat16* __restrict__ outh, __nv_bfloat16* __restrict__ outl)
{
    extern __shared__ __align__(16) char sm[];
    const int tid = threadIdx.x;
    const int wid = tid >> 5, lane = tid & 31;
    const int wm = wid & 1, wn = wid >> 1;
    const int bh = blockIdx.z, b = bh >> 4, h = bh & 15;
    const int r0 = blockIdx.y * 128;
    const uint32_t smb = smem_u32(sm);

    const int nc = NP / KC;
    const int klim_ = NP;
    float acc[4][8][4] = {};

    const __nv_bfloat16* srcs[4] = {
        ph + (size_t)bh*N_*NP, pl + (size_t)bh*N_*NP,
        vth + (size_t)bh*D_*NPV, vtl + (size_t)bh*D_*NPV };
    const size_t lds[4] = {NP, NP, NPV, NPV};
    const int rbase[4] = {r0, r0, 0, 0};
    const int rlim[4]  = {N_, N_, D_, D_};

    MMA_MAINLOOP(nc)

    #pragma unroll
    for (int mi = 0; mi < 4; mi++) {
        int rA = r0 + wm*64 + mi*16 + (lane >> 2);
        #pragma unroll
        for (int ni = 0; ni < 8; ni++) {
            int cA = wn*64 + ni*8 + (lane & 3)*2;
            #pragma unroll
            for (int hrow = 0; hrow < 2; hrow++) {
                int r = rA + hrow*8;
                if (r >= N_) continue;
                #pragma unroll
                for (int dc = 0; dc < 2; dc++) {
                    int cg = cA + dc;
                    if (cg >= D_) continue;
                    size_t oi = ((size_t)(b*N_ + r))*C_ + h*D_ + cg;
                    float vv = acc[mi][ni][hrow*2 + dc];
                    __nv_bfloat16 hi = __float2bfloat16(vv);
                    outh[oi] = hi;
                    outl[oi] = __float2bfloat16(vv - __bfloat162float(hi));
                }
            }
        }
    }
}

// ----------------------- V transpose + split -----------------------------------
__global__ void vt_kernel(const float* __restrict__ v,
                          __nv_bfloat16* __restrict__ vth, __nv_bfloat16* __restrict__ vtl)
{
    __shared__ float ts[64][D_+1];
    const int bh = blockIdx.y, b = bh >> 4, h = bh & 15;
    const int tt = blockIdx.x;
    for (int i = threadIdx.x; i < 64*D_; i += 256) {
        int tok = i / D_, d = i % D_;
        int n = tt*64 + tok;
        ts[tok][d] = (n < N_) ? v[((size_t)(b*N_ + n))*C_ + h*D_ + d] : 0.f;
    }
    __syncthreads();
    for (int i = threadIdx.x; i < D_*64; i += 256) {
        int d = i / 64, tok = i % 64;
        int n = tt*64 + tok;
        if (n < NPV) {
            float vv = ts[tok][d];
            __nv_bfloat16 hi = __float2bfloat16(vv);
            size_t oi = ((size_t)bh*D_ + d)*NPV + n;
            vth[oi] = hi;
            vtl[oi] = __float2bfloat16(vv - __bfloat162float(hi));
        }
    }
}

// ------------------------------ weight splits ----------------------------------
__global__ void tsplit_qkv_kernel(const float* __restrict__ Wq, const float* __restrict__ Wk,
                                  const float* __restrict__ Wv,
                                  __nv_bfloat16* __restrict__ Th, __nv_bfloat16* __restrict__ Tl)
{
    int i = blockIdx.x*256 + threadIdx.x;
    if (i >= 3*C_*C_) return;
    int which = i / (C_*C_);
    int j = i - which*(C_*C_);
    int n = j / C_, kk = j % C_;
    const float* W = (which == 0) ? Wq : (which == 1) ? Wk : Wv;
    float x = W[(size_t)kk*C_ + n];
    __nv_bfloat16 hi = __float2bfloat16(x);
    Th[i] = hi;
    Tl[i] = __float2bfloat16(x - __bfloat162float(hi));
}

__global__ void tsplit_kernel(const float* __restrict__ W,
                              __nv_bfloat16* __restrict__ Th, __nv_bfloat16* __restrict__ Tl,
                              int K, int Nn)
{
    int i = blockIdx.x*256 + threadIdx.x;
    if (i >= Nn*K) return;
    int n = i / K, kk = i % K;
    float x = W[(size_t)kk*Nn + n];
    __nv_bfloat16 hi = __float2bfloat16(x);
    Th[i] = hi;
    Tl[i] = __float2bfloat16(x - __bfloat162float(hi));
}

__global__ void bconcat_kernel(const float* __restrict__ bq, const float* __restrict__ bk,
                               const float* __restrict__ bv, float* __restrict__ bqkv)
{
    int i = blockIdx.x*256 + threadIdx.x;
    if (i >= 3*C_) return;
    bqkv[i] = (i < C_) ? bq[i] : (i < 2*C_) ? bk[i - C_] : bv[i - 2*C_];
}

// ------------------------------- LayerNorm (+ split) --------------------------
__global__ void ln_kernel(const float* __restrict__ x, const float* __restrict__ g,
                          const float* __restrict__ bb, float* __restrict__ y,
                          __nv_bfloat16* __restrict__ yh, __nv_bfloat16* __restrict__ yl,
                          int cols)
{
    int row = blockIdx.x;
    const float* xr = x + (size_t)row * cols;
    float* yr = y + (size_t)row * cols;
    __shared__ float rs[256], rs2[256];
    float s = 0.f, s2 = 0.f;
    for (int c = threadIdx.x; c < cols; c += 256) { float v = xr[c]; s += v; s2 += v*v; }
    rs[threadIdx.x] = s; rs2[threadIdx.x] = s2; __syncthreads();
    for (int o = 128; o > 0; o >>= 1) {
        if (threadIdx.x < o) { rs[threadIdx.x] += rs[threadIdx.x+o]; rs2[threadIdx.x] += rs2[threadIdx.x+o]; }
        __syncthreads();
    }
    float mean = rs[0] / cols;
    float var  = rs2[0] / cols - mean*mean;
    float rstd = rsqrtf(var + EPSLN);
    for (int c = threadIdx.x; c < cols; c += 256) {
        float v = (xr[c]-mean)*rstd*g[c] + bb[c];
        yr[c] = v;
        if (yh) {
            __nv_bfloat16 hi = __float2bfloat16(v);
            yh[(size_t)row*cols + c] = hi;
            yl[(size_t)row*cols + c] = __float2bfloat16(v - __bfloat162float(hi));
        }
    }
}

// ----------------- metric pipeline (df64 compensated fp32) --------------------
__global__ void wkbar_kernel(const float* __restrict__ wk, float2* __restrict__ wk2)
{
    int idx = blockIdx.x*256 + threadIdx.x;
    if (idx >= C_*D_) return;
    int c = idx / D_, d = idx % D_;
    double s = 0.0;
    #pragma unroll
    for (int hh = 0; hh < H_; hh++) s += (double)wk[(size_t)c*C_ + hh*D_ + d];
    s *= (1.0/H_);
    float hi = (float)s;
    wk2[idx] = make_float2(hi, (float)(s - (double)hi));
}

// K-split metric GEMM: part p handles k in [p*384, (p+1)*384)
#define MT 64
__global__ __launch_bounds__(256) void metricgemm_kernel(
    const float* __restrict__ xln, const float2* __restrict__ wk2,
    double* __restrict__ rawP, int Mtok)
{
    __shared__ float  As[16][MT+1];
    __shared__ float2 Bs[16][D_];
    const int t0 = blockIdx.x * MT;
    const int part = blockIdx.y;
    const int kbeg = part * (C_/3), kend = kbeg + (C_/3);
    const int tl = threadIdx.x & 63, grp = threadIdx.x >> 6;
    float shi[18] = {}, slo[18] = {};
    for (int k0 = kbeg; k0 < kend; k0 += 16) {
        for (int i = threadIdx.x; i < MT*16; i += 256) {
            int kk = i & 15, tok = i >> 4;
            As[kk][tok] = (t0 + tok < Mtok) ? xln[(size_t)(t0+tok)*C_ + k0 + kk] : 0.f;
        }
        for (int i = threadIdx.x; i < 16*D_; i += 256) {
            int kk = i / D_, d = i % D_;
            Bs[kk][d] = wk2[(size_t)(k0+kk)*D_ + d];
        }
        __syncthreads();
        #pragma unroll
        for (int kk = 0; kk < 16; kk++) {
            float a = As[kk][tl];
            #pragma unroll
            for (int j = 0; j < 18; j++) {
                float2 bv = Bs[kk][grp*18 + j];
                df_acc(shi[j], slo[j], a, bv.x, bv.y);
            }
        }
        __syncthreads();
    }
    if (t0 + tl < Mtok) {
        #pragma unroll
        for (int j = 0; j < 18; j++)
            rawP[((size_t)part*Mtok + t0+tl)*D_ + grp*18 + j] = (double)shi[j] + (double)slo[j];
    }
}

__global__ void norm_kernel(const double* __restrict__ rawP, double* __restrict__ mn,
                            const float* __restrict__ bk, int Mtok)
{
    int bn = blockIdx.x;
    __shared__ double val[D_];
    __shared__ double red[128];
    double v = 0.0;
    if (threadIdx.x < D_) {
        double bmean = 0.0;
        #pragma unroll
        for (int hh = 0; hh < H_; hh++) bmean += (double)bk[hh*D_ + threadIdx.x];
        v = rawP[(size_t)bn*D_ + threadIdx.x]
          + rawP[((size_t)Mtok + bn)*D_ + threadIdx.x]
          + rawP[((size_t)2*Mtok + bn)*D_ + threadIdx.x]
          + bmean*(1.0/H_);
        val[threadIdx.x] = v;
    }
    red[threadIdx.x] = v*v; __syncthreads();
    for (int o = 64; o > 0; o >>= 1) {
        if (threadIdx.x < o) red[threadIdx.x] += red[threadIdx.x+o];
        __syncthreads();
    }
    double inv = 1.0 / sqrt(red[0]);
    if (threadIdx.x < D_) mn[(size_t)bn*D_ + threadIdx.x] = val[threadIdx.x]*inv;
}

// ----------------------- softmax: S -> split bf16 P ----------------------------
__global__ __launch_bounds__(256) void softmax_kernel(
    const float* __restrict__ S,
    __nv_bfloat16* __restrict__ ph, __nv_bfloat16* __restrict__ pl)
{
    const float* row = S + (size_t)blockIdx.x * NP;
    size_t base = (size_t)blockIdx.x * NP;
    __shared__ float red[256];
    float ev[3];
    float mx = -1e30f;
    #pragma unroll
    for (int it = 0; it < 3; it++) {
        int j = threadIdx.x + it*256;
        float v = (j < N_) ? row[j] : -1e30f;
        ev[it] = v;
        mx = fmaxf(mx, v);
    }
    red[threadIdx.x] = mx; __syncthreads();
    for (int o = 128; o > 0; o >>= 1) {
        if (threadIdx.x < o) red[threadIdx.x] = fmaxf(red[threadIdx.x], red[threadIdx.x+o]);
        __syncthreads();
    }
    mx = red[0]; __syncthreads();
    float sum = 0.f;
    #pragma unroll
    for (int it = 0; it < 3; it++) {
        int j = threadIdx.x + it*256;
        if (j < N_) { float e = __expf(ev[it] - mx); ev[it] = e; sum += e; }
    }
    red[threadIdx.x] = sum; __syncthreads();
    for (int o = 128; o > 0; o >>= 1) {
        if (threadIdx.x < o) red[threadIdx.x] += red[threadIdx.x+o];
        __syncthreads();
    }
    float inv = 1.f / red[0];
    #pragma unroll
    for (int it = 0; it < 3; it++) {
        int j = threadIdx.x + it*256;
        if (j < N_) {
            float p = ev[it] * inv;
            __nv_bfloat16 hi = __float2bfloat16(p);
            ph[base + j] = hi;
            pl[base + j] = __float2bfloat16(p - __bfloat162float(hi));
        }
    }
    if (threadIdx.x < NP - N_) {
        ph[base + N_ + threadIdx.x] = __float2bfloat16(0.f);
        pl[base + N_ + threadIdx.x] = __float2bfloat16(0.f);
    }
}

// ------------------------- ToMe: per-a-token best match (df64) ----------------
__global__ void tome_score_kernel(const double* __restrict__ mn,
                                  double* __restrict__ nmax, int* __restrict__ nidx)
{
    int b = blockIdx.y, i = blockIdx.x;
    __shared__ float avh[D_], avl[D_];
    __shared__ double bm[128]; __shared__ int bi[128];
    if (threadIdx.x < D_) {
        double a = mn[((size_t)b*N_ + 2*i)*D_ + threadIdx.x];
        float hh = (float)a;
        avh[threadIdx.x] = hh;
        avl[threadIdx.x] = (float)(a - (double)hh);
    }
    __syncthreads();
    double best = -1e300; int bj = 0x7fffffff;
    for (int j = threadIdx.x; j < NB; j += 128) {
        const double* r = mn + ((size_t)b*N_ + 2*j + 1)*D_;
        float dh = 0.f, dl = 0.f;
        #pragma unroll 8
        for (int d = 0; d < D_; d++) {
            double rv = r[d];
            float rh = (float)rv, rl = (float)(rv - (double)rh);
            float ah = avh[d];
            df_acc(dh, dl, ah, rh, rl);
            dl += avl[d]*rh;
        }
        double dot = (double)dh + (double)dl;
        if (dot > best) { best = dot; bj = j; }
    }
    bm[threadIdx.x] = best; bi[threadIdx.x] = bj; __syncthreads();
    for (int o = 64; o > 0; o >>= 1) {
        if (threadIdx.x < o) {
            double ov = bm[threadIdx.x+o]; int oi = bi[threadIdx.x+o];
            if (ov > bm[threadIdx.x] || (ov == bm[threadIdx.x] && oi < bi[threadIdx.x])) {
                bm[threadIdx.x] = ov; bi[threadIdx.x] = oi;
            }
        }
        __syncthreads();
    }
    if (threadIdx.x == 0) { nmax[(size_t)b*NA + i] = bm[0]; nidx[(size_t)b*NA + i] = bi[0]; }
}

__global__ void rank_kernel(const double* __restrict__ nmax, int* __restrict__ edge)
{
    int b = blockIdx.x;
    __shared__ double nm[NA];
    if (threadIdx.x < NA) nm[threadIdx.x] = nmax[(size_t)b*NA + threadIdx.x];
    __syncthreads();
    if (threadIdx.x < NA) {
        double mi = nm[threadIdx.x]; int cnt = 0;
        for (int j = 0; j < NA; j++)
            cnt += (nm[j] > mi) || (nm[j] == mi && j < (int)threadIdx.x);
        edge[(size_t)b*NA + cnt] = threadIdx.x;
    }
}

// ----------------- ToMe merge + LN2 + split (fused) ----------------------------
__global__ void merge_ln_kernel(const float* __restrict__ h, const int* __restrict__ edge,
                                const int* __restrict__ nidx,
                                const float* __restrict__ g, const float* __restrict__ bb,
                                float* __restrict__ mg,
                                __nv_bfloat16* __restrict__ yh, __nv_bfloat16* __restrict__ yl)
{
    int b = blockIdx.y, pos = blockIdx.x;
    __shared__ int ssrc[R_], sdst[R_];
    __shared__ float rowv[C_];
    __shared__ float rs[256], rs2[256];
    if (threadIdx.x < R_) {
        int i = edge[(size_t)b*NA + threadIdx.x];
        ssrc[threadIdx.x] = i;
        sdst[threadIdx.x] = nidx[(size_t)b*NA + i];
    }
    __syncthreads();
    float* mrow = mg + ((size_t)b*NM + pos)*C_;
    if (pos < NU) {
        int i = edge[(size_t)b*NA + R_ + pos];
        const float* sr = h + ((size_t)b*N_ + 2*i)*C_;
        for (int c = threadIdx.x; c < C_; c += 256) rowv[c] = sr[c];
    } else {
        int j = pos - NU;
        const float* dr = h + ((size_t)b*N_ + 2*j + 1)*C_;
        int cnt = 1;
        #pragma unroll
        for (int s = 0; s < R_; s++) cnt += (sdst[s] == j);
        float invc = 1.f / (float)cnt;
        for (int c = threadIdx.x; c < C_; c += 256) {
            float vv = dr[c];
            #pragma unroll
            for (int s = 0; s < R_; s++)
                if (sdst[s] == j) vv += h[((size_t)b*N_ + 2*ssrc[s])*C_ + c];
            rowv[c] = vv*invc;
        }
    }
    __syncthreads();
    float s = 0.f, s2 = 0.f;
    for (int c = threadIdx.x; c < C_; c += 256) { float v = rowv[c]; s += v; s2 += v*v; }
    rs[threadIdx.x] = s; rs2[threadIdx.x] = s2; __syncthreads();
    for (int o = 128; o > 0; o >>= 1) {
        if (threadIdx.x < o) { rs[threadIdx.x] += rs[threadIdx.x+o]; rs2[threadIdx.x] += rs2[threadIdx.x+o]; }
        __syncthreads();
    }
    float mean = rs[0] / C_;
    float var  = rs2[0] / C_ - mean*mean;
    float rstd = rsqrtf(var + EPSLN);
    size_t base = ((size_t)b*NM + pos)*C_;
    for (int c = threadIdx.x; c < C_; c += 256) {
        float raw = rowv[c];
        mrow[c] = raw;
        float v = (raw-mean)*rstd*g[c] + bb[c];
        __nv_bfloat16 hi = __float2bfloat16(v);
        yh[base + c] = hi;
        yl[base + c] = __float2bfloat16(v - __bfloat162float(hi));
    }
}

// --------------------------------- driver -------------------------------------
extern "C" void kernel_launch(void* const* d_in, const int* in_sizes, int n_in,
                              void* d_out, int out_size)
{
    const float* hs   = (const float*)d_in[0];
    const float* mask = (const float*)d_in[1];
    const float* wq   = (const float*)d_in[2];
    const float* bq   = (const float*)d_in[3];
    const float* wk   = (const float*)d_in[4];
    const float* bk   = (const float*)d_in[5];
    const float* wv   = (const float*)d_in[6];
    const float* bv   = (const float*)d_in[7];
    const float* wo   = (const float*)d_in[8];
    const float* bo   = (const float*)d_in[9];
    const float* ln1w = (const float*)d_in[10];
    const float* ln1b = (const float*)d_in[11];
    const float* ln2w = (const float*)d_in[12];
    const float* ln2b = (const float*)d_in[13];
    const float* fc1w = (const float*)d_in[14];
    const float* fc1b = (const float*)d_in[15];
    const float* fc2w = (const float*)d_in[16];
    const float* fc2b = (const float*)d_in[17];

    float *xln, *v, *h, *sc, *mg, *bqkv;
    float2 *wk2;
    double *mnP, *mnD, *nmax;
    int *nidx, *edge;
    __nv_bfloat16 *xh,*xl,*qh,*ql,*kh,*kl,*ph,*pl,*vth,*vtl,*aoh,*aol,*h2h,*h2l,*f1h,*f1l;
    __nv_bfloat16 *wqkvth,*wqkvtl,*woth,*wotl,*w1th,*w1tl,*w2th,*w2tl;
    cudaGetSymbolAddress((void**)&xln,   g_xln);
    cudaGetSymbolAddress((void**)&v,     g_v);
    cudaGetSymbolAddress((void**)&h,     g_h);
    cudaGetSymbolAddress((void**)&sc,    g_sc);
    cudaGetSymbolAddress((void**)&wk2,   g_wk2);
    cudaGetSymbolAddress((void**)&mnP,   g_mnP);
    cudaGetSymbolAddress((void**)&mnD,   g_mnD);
    cudaGetSymbolAddress((void**)&nmax,  g_nmax);
    cudaGetSymbolAddress((void**)&nidx,  g_nidx);
    cudaGetSymbolAddress((void**)&edge,  g_edge);
    cudaGetSymbolAddress((void**)&mg,    g_mg);
    cudaGetSymbolAddress((void**)&bqkv,  g_bqkv);
    cudaGetSymbolAddress((void**)&xh,    g_xh);
    cudaGetSymbolAddress((void**)&xl,    g_xl);
    cudaGetSymbolAddress((void**)&qh,    g_qh);
    cudaGetSymbolAddress((void**)&ql,    g_ql);
    cudaGetSymbolAddress((void**)&kh,    g_kh);
    cudaGetSymbolAddress((void**)&kl,    g_kl);
    cudaGetSymbolAddress((void**)&ph,    g_ph);
    cudaGetSymbolAddress((void**)&pl,    g_pl);
    cudaGetSymbolAddress((void**)&vth,   g_vth);
    cudaGetSymbolAddress((void**)&vtl,   g_vtl);
    cudaGetSymbolAddress((void**)&aoh,   g_aoh);
    cudaGetSymbolAddress((void**)&aol,   g_aol);
    cudaGetSymbolAddress((void**)&h2h,   g_h2h);
    cudaGetSymbolAddress((void**)&h2l,   g_h2l);
    cudaGetSymbolAddress((void**)&f1h,   g_f1h);
    cudaGetSymbolAddress((void**)&f1l,   g_f1l);
    cudaGetSymbolAddress((void**)&wqkvth, g_wqkvth);
    cudaGetSymbolAddress((void**)&wqkvtl, g_wqkvtl);
    cudaGetSymbolAddress((void**)&woth,  g_woth);
    cudaGetSymbolAddress((void**)&wotl,  g_wotl);
    cudaGetSymbolAddress((void**)&w1th,  g_w1th);
    cudaGetSymbolAddress((void**)&w1tl,  g_w1tl);
    cudaGetSymbolAddress((void**)&w2th,  g_w2th);
    cudaGetSymbolAddress((void**)&w2tl,  g_w2tl);

    cudaFuncSetAttribute(mma_gemm,     cudaFuncAttributeMaxDynamicSharedMemorySize, MM_SMEM);
    cudaFuncSetAttribute(mma_gemm_qkv, cudaFuncAttributeMaxDynamicSharedMemorySize, MM_SMEM);
    cudaFuncSetAttribute(qk_mma,       cudaFuncAttributeMaxDynamicSharedMemorySize, MM_SMEM);
    cudaFuncSetAttribute(av_mma,       cudaFuncAttributeMaxDynamicSharedMemorySize, MM_SMEM);

    const int MN1 = B_*N_;    // 5832
    const int MN2 = B_*NM;    // 5648
    const int GY1 = (MN1+127)/128;
    const int GY2 = (MN2+127)/128;
    const int QT  = (N_+127)/128;

    // launches 1-3: combined qkv weight split, bias concat, LN1
    tsplit_qkv_kernel<<<(3*C_*C_+255)/256, 256>>>(wq, wk, wv, wqkvth, wqkvtl);
    bconcat_kernel<<<(3*C_+255)/256, 256>>>(bq, bk, bv, bqkv);
    ln_kernel<<<MN1, 256>>>(hs, ln1w, ln1b, xln, xh, xl, C_);

    // launch 4: fused QKV (profiled launch)
    mma_gemm_qkv<<<dim3(3*C_/128, GY1), MM_THREADS, MM_SMEM>>>(xh, xl, wqkvth, wqkvtl, bqkv,
                                                               qh, ql, kh, kl, v, MN1);

    // metric pipeline (K-split x3)
    wkbar_kernel<<<(C_*D_+255)/256, 256>>>(wk, wk2);
    metricgemm_kernel<<<dim3((MN1+MT-1)/MT, 3), 256>>>(xln, wk2, mnP, MN1);
    norm_kernel<<<MN1, 128>>>(mnP, mnD, bk, MN1);

    // attention
    vt_kernel<<<dim3((NPV+63)/64, B_*H_), 256>>>(v, vth, vtl);
    qk_mma<<<dim3(QT, QT, B_*H_), MM_THREADS, MM_SMEM>>>(qh, ql, kh, kl, mask, sc);
    softmax_kernel<<<B_*H_*N_, 256>>>(sc, ph, pl);
    av_mma<<<dim3(1, QT, B_*H_), MM_THREADS, MM_SMEM>>>(ph, pl, vth, vtl, aoh, aol);

    // output projection + residual
    tsplit_kernel<<<(C_*C_+255)/256, 256>>>(wo, woth, wotl, C_, C_);
    mma_gemm<<<dim3(C_/128, GY1), MM_THREADS, MM_SMEM>>>(aoh, aol, woth, wotl, bo, hs, h, nullptr, nullptr, MN1, C_, C_, 0);

    // ToMe + fused merge/LN2/split
    tome_score_kernel<<<dim3(NA, B_), 128>>>(mnD, nmax, nidx);
    rank_kernel<<<B_, 512>>>(nmax, edge);
    merge_ln_kernel<<<dim3(NM, B_), 256>>>(h, edge, nidx, ln2w, ln2b, mg, h2h, h2l);

    // MLP
    tsplit_kernel<<<(F_*C_+255)/256, 256>>>(fc1w, w1th, w1tl, C_, F_);
    tsplit_kernel<<<(F_*C_+255)/256, 256>>>(fc2w, w2th, w2tl, F_, C_);
    mma_gemm<<<dim3((F_+127)/128, GY2), MM_THREADS, MM_SMEM>>>(h2h, h2l, w1th, w1tl, fc1b, nullptr, nullptr, f1h, f1l, MN2, F_, C_, 1);
    mma_gemm<<<dim3(C_/128, GY2), MM_THREADS, MM_SMEM>>>(f1h, f1l, w2th, w2tl, fc2b, mg, (float*)d_out, nullptr, nullptr, MN2, C_, F_, 0);
}

// round 17
// speedup vs baseline: 1.1602x; 1.1602x over previous
#include <cuda_runtime.h>
#include <cuda_bf16.h>
#include <math.h>
#include <stdint.h>

#define B_ 8
#define N_ 729
#define C_ 1152
#define H_ 16
#define D_ 72
#define F_ 4304
#define R_ 23
#define NA 365
#define NB 364
#define NM 706
#define NU 342
#define NP 736
#define NPV 736
#define EPSLN 1e-6f
#define SCALE_ 0.1178511301977579f

// ------------------------- scratch (static device globals) -------------------
__device__ float  g_xln[B_*N_*C_];
__device__ float  g_v  [B_*N_*C_];
__device__ float  g_h  [B_*N_*C_];
__device__ __align__(16) float g_sc[(size_t)B_*H_*N_*NP];
__device__ float2 g_wk2[C_*D_];
__device__ double g_mnP[3*B_*N_*D_];
__device__ double g_mnD[B_*N_*D_];
__device__ double g_nmax[B_*NA];
__device__ int    g_nidx[B_*NA];
__device__ int    g_edge[B_*NA];
__device__ float  g_mg [B_*NM*C_];
__device__ float  g_bqkv[3*C_];
// bf16 split activations
__device__ __align__(16) __nv_bfloat16 g_xh [B_*N_*C_];
__device__ __align__(16) __nv_bfloat16 g_xl [B_*N_*C_];
__device__ __align__(16) __nv_bfloat16 g_qh [B_*N_*C_];
__device__ __align__(16) __nv_bfloat16 g_ql [B_*N_*C_];
__device__ __align__(16) __nv_bfloat16 g_kh [B_*N_*C_];
__device__ __align__(16) __nv_bfloat16 g_kl [B_*N_*C_];
__device__ __align__(16) __nv_bfloat16 g_ph [(size_t)B_*H_*N_*NP];
__device__ __align__(16) __nv_bfloat16 g_pl [(size_t)B_*H_*N_*NP];
__device__ __align__(16) __nv_bfloat16 g_vth[B_*H_*D_*NPV];
__device__ __align__(16) __nv_bfloat16 g_vtl[B_*H_*D_*NPV];
__device__ __align__(16) __nv_bfloat16 g_aoh[B_*N_*C_];
__device__ __align__(16) __nv_bfloat16 g_aol[B_*N_*C_];
__device__ __align__(16) __nv_bfloat16 g_h2h[B_*NM*C_];
__device__ __align__(16) __nv_bfloat16 g_h2l[B_*NM*C_];
__device__ __align__(16) __nv_bfloat16 g_f1h[B_*NM*F_];
__device__ __align__(16) __nv_bfloat16 g_f1l[B_*NM*F_];
// bf16 split transposed weights [N][K]
__device__ __align__(16) __nv_bfloat16 g_wqkvth[3*C_*C_];
__device__ __align__(16) __nv_bfloat16 g_wqkvtl[3*C_*C_];
__device__ __align__(16) __nv_bfloat16 g_woth[C_*C_];
__device__ __align__(16) __nv_bfloat16 g_wotl[C_*C_];
__device__ __align__(16) __nv_bfloat16 g_w1th[(size_t)F_*C_];
__device__ __align__(16) __nv_bfloat16 g_w1tl[(size_t)F_*C_];
__device__ __align__(16) __nv_bfloat16 g_w2th[(size_t)C_*F_];
__device__ __align__(16) __nv_bfloat16 g_w2tl[(size_t)C_*F_];

// --------------------------- asm helpers --------------------------------------
static __device__ __forceinline__ uint32_t smem_u32(const void* p) {
    uint32_t a;
    asm("{ .reg .u64 t; cvta.to.shared.u64 t, %1; cvt.u32.u64 %0, t; }" : "=r"(a) : "l"(p));
    return a;
}
static __device__ __forceinline__ void ldsm_x4(uint32_t addr, uint32_t* r) {
    asm volatile("ldmatrix.sync.aligned.m8n8.x4.shared.b16 {%0,%1,%2,%3}, [%4];"
        : "=r"(r[0]), "=r"(r[1]), "=r"(r[2]), "=r"(r[3]) : "r"(addr));
}
static __device__ __forceinline__ void mma_bf16(float* d, const uint32_t* a, const uint32_t* b) {
    asm volatile("mma.sync.aligned.m16n8k16.row.col.f32.bf16.bf16.f32 "
        "{%0,%1,%2,%3}, {%4,%5,%6,%7}, {%8,%9}, {%0,%1,%2,%3};"
        : "+f"(d[0]), "+f"(d[1]), "+f"(d[2]), "+f"(d[3])
        : "r"(a[0]), "r"(a[1]), "r"(a[2]), "r"(a[3]), "r"(b[0]), "r"(b[1]));
}
static __device__ __forceinline__ void cp_async16(uint32_t saddr, const void* gaddr, int sz) {
    asm volatile("cp.async.ca.shared.global [%0], [%1], 16, %2;"
        :: "r"(saddr), "l"(gaddr), "r"(sz) : "memory");
}
#define CP_COMMIT() asm volatile("cp.async.commit_group;" ::: "memory")
#define CP_WAIT1()  asm volatile("cp.async.wait_group 1;" ::: "memory")

static __device__ __forceinline__ void df_acc(float& hi, float& lo, float a, float bh, float bl)
{
    float p  = a * bh;
    float e  = fmaf(a, bh, -p);
    float t  = hi + p;
    float bb = t - hi;
    float err = (hi - (t - bb)) + (p - bb);
    hi = t;
    lo += err + e + a * bl;
}

__device__ __forceinline__ float gelu_tanh(float x)
{
    float x3 = x*x*x;
    float t = tanhf(0.7978845608028654f*(x + 0.044715f*x3));
    return 0.5f*x*(1.f + t);
}

// =================== shared MMA core (round-13 best config) ====================
// 256 threads, 8 warps (4x2), warp tile 32x64, 2-stage cp.async, LDH=40 pad
#define KC 32
#define LDH 40
#define TILE_B (128*LDH*2)
#define STAGE_B (4*TILE_B)       // 40960
#define MM_SMEM (2*STAGE_B)      // 81920
#define MM_THREADS 256

static __device__ __forceinline__ void mma_stage_compute(
    uint32_t smb, int s, int wm, int wn, int lane, float acc[2][8][4])
{
    uint32_t sa  = smb + s*STAGE_B;
    uint32_t aT  = sa;
    uint32_t alT = sa + TILE_B;
    uint32_t bhT = sa + 2*TILE_B;
    uint32_t blT = sa + 3*TILE_B;
    #pragma unroll
    for (int k16 = 0; k16 < 2; k16++) {
        int kb = k16*32;
        uint32_t Ah2[2][4], Al2[2][4];
        #pragma unroll
        for (int mi = 0; mi < 2; mi++) {
            int rowl = wm*32 + mi*16 + (lane & 15);
            uint32_t off = rowl*(LDH*2) + kb + ((lane >> 4) * 16);
            ldsm_x4(aT + off, Ah2[mi]);
            ldsm_x4(alT + off, Al2[mi]);
        }
        #pragma unroll
        for (int nj = 0; nj < 4; nj++) {
            int rowl = wn*64 + nj*16 + (lane & 7) + ((lane >> 4) * 8);
            uint32_t off = rowl*(LDH*2) + kb + (((lane >> 3) & 1) * 16);
            uint32_t bh[4], bl[4];
            ldsm_x4(bhT + off, bh);
            ldsm_x4(blT + off, bl);
            #pragma unroll
            for (int mi = 0; mi < 2; mi++) {
                mma_bf16(acc[mi][nj*2],   Ah2[mi], bh);
                mma_bf16(acc[mi][nj*2],   Ah2[mi], bl);
                mma_bf16(acc[mi][nj*2],   Al2[mi], bh);
                mma_bf16(acc[mi][nj*2+1], Ah2[mi], bh+2);
                mma_bf16(acc[mi][nj*2+1], Ah2[mi], bl+2);
                mma_bf16(acc[mi][nj*2+1], Al2[mi], bh+2);
            }
        }
    }
}

static __device__ __forceinline__ void mma_load_stage(
    uint32_t smb, int c, int tid,
    const __nv_bfloat16* const* srcs, const size_t* lds,
    const int* rbase, const int* rlim, int klim)
{
    int s = c & 1;
    int k0 = c * KC;
    #pragma unroll
    for (int t = 0; t < 4; t++) {
        #pragma unroll
        for (int it = 0; it < 2; it++) {
            int idx = tid + it*MM_THREADS;
            int row = idx >> 2, g = idx & 3;
            int grow = rbase[t] + row, gk = k0 + g*8;
            bool ok = (grow < rlim[t]) && (gk < klim);
            const void* gaddr = ok ? (const void*)(srcs[t] + (size_t)grow*lds[t] + gk)
                                   : (const void*)srcs[t];
            uint32_t saddr = smb + s*STAGE_B + t*TILE_B + row*(LDH*2) + g*16;
            cp_async16(saddr, gaddr, ok ? 16 : 0);
        }
    }
    CP_COMMIT();
}

// --------------------- general dense GEMM (weights) ----------------------------
__global__ __launch_bounds__(MM_THREADS,2) void mma_gemm(
    const __nv_bfloat16* __restrict__ Ah, const __nv_bfloat16* __restrict__ Al,
    const __nv_bfloat16* __restrict__ BTh, const __nv_bfloat16* __restrict__ BTl,
    const float* __restrict__ bias, const float* __restrict__ add,
    float* __restrict__ Cout,
    __nv_bfloat16* __restrict__ Oh, __nv_bfloat16* __restrict__ Ol,
    int M, int Nn, int K, int act)
{
    extern __shared__ __align__(16) char sm[];
    const int tid = threadIdx.x;
    const int wid = tid >> 5, lane = tid & 31;
    const int wm = wid & 3, wn = wid >> 2;
    const int n0 = blockIdx.x * 128, r0 = blockIdx.y * 128;
    const uint32_t smb = smem_u32(sm);

    const int nc = (K + KC - 1) / KC;
    float acc[2][8][4] = {};

    const __nv_bfloat16* srcs[4] = {Ah, Al, BTh, BTl};
    const size_t lds[4] = {(size_t)K, (size_t)K, (size_t)K, (size_t)K};
    const int rbase[4] = {r0, r0, n0, n0};
    const int rlim[4]  = {M, M, Nn, Nn};

    mma_load_stage(smb, 0, tid, srcs, lds, rbase, rlim, K);
    for (int c = 0; c < nc; c++) {
        __syncthreads();
        if (c+1 < nc) mma_load_stage(smb, c+1, tid, srcs, lds, rbase, rlim, K);
        else          CP_COMMIT();
        CP_WAIT1();
        __syncthreads();
        mma_stage_compute(smb, c & 1, wm, wn, lane, acc);
    }

    #pragma unroll
    for (int mi = 0; mi < 2; mi++) {
        int rA = r0 + wm*32 + mi*16 + (lane >> 2);
        #pragma unroll
        for (int ni = 0; ni < 8; ni++) {
            int cA = n0 + wn*64 + ni*8 + (lane & 3)*2;
            #pragma unroll
            for (int hrow = 0; hrow < 2; hrow++) {
                int r = rA + hrow*8;
                if (r >= M) continue;
                #pragma unroll
                for (int dc = 0; dc < 2; dc++) {
                    int cg = cA + dc;
                    if (cg >= Nn) continue;
                    float vv = acc[mi][ni][hrow*2 + dc] + (bias ? bias[cg] : 0.f);
                    if (act) vv = gelu_tanh(vv);
                    if (add) vv += add[(size_t)r*Nn + cg];
                    if (Cout) Cout[(size_t)r*Nn + cg] = vv;
                    if (Oh) {
                        __nv_bfloat16 hi = __float2bfloat16(vv);
                        Oh[(size_t)r*Nn + cg] = hi;
                        Ol[(size_t)r*Nn + cg] = __float2bfloat16(vv - __bfloat162float(hi));
                    }
                }
            }
        }
    }
}

// --------------------- fused QKV GEMM (Nn = 3*C) -------------------------------
__global__ __launch_bounds__(MM_THREADS,2) void mma_gemm_qkv(
    const __nv_bfloat16* __restrict__ Ah, const __nv_bfloat16* __restrict__ Al,
    const __nv_bfloat16* __restrict__ BTh, const __nv_bfloat16* __restrict__ BTl,
    const float* __restrict__ bias,
    __nv_bfloat16* __restrict__ qh, __nv_bfloat16* __restrict__ ql,
    __nv_bfloat16* __restrict__ kh, __nv_bfloat16* __restrict__ kl,
    float* __restrict__ v, int M)
{
    extern __shared__ __align__(16) char sm[];
    const int tid = threadIdx.x;
    const int wid = tid >> 5, lane = tid & 31;
    const int wm = wid & 3, wn = wid >> 2;
    const int n0 = blockIdx.x * 128, r0 = blockIdx.y * 128;
    const uint32_t smb = smem_u32(sm);
    const int K = C_, Nn = 3*C_;

    const int nc = (K + KC - 1) / KC;
    float acc[2][8][4] = {};

    const __nv_bfloat16* srcs[4] = {Ah, Al, BTh, BTl};
    const size_t lds[4] = {(size_t)K, (size_t)K, (size_t)K, (size_t)K};
    const int rbase[4] = {r0, r0, n0, n0};
    const int rlim[4]  = {M, M, Nn, Nn};

    mma_load_stage(smb, 0, tid, srcs, lds, rbase, rlim, K);
    for (int c = 0; c < nc; c++) {
        __syncthreads();
        if (c+1 < nc) mma_load_stage(smb, c+1, tid, srcs, lds, rbase, rlim, K);
        else          CP_COMMIT();
        CP_WAIT1();
        __syncthreads();
        mma_stage_compute(smb, c & 1, wm, wn, lane, acc);
    }

    #pragma unroll
    for (int mi = 0; mi < 2; mi++) {
        int rA = r0 + wm*32 + mi*16 + (lane >> 2);
        #pragma unroll
        for (int ni = 0; ni < 8; ni++) {
            int cA = n0 + wn*64 + ni*8 + (lane & 3)*2;
            #pragma unroll
            for (int hrow = 0; hrow < 2; hrow++) {
                int r = rA + hrow*8;
                if (r >= M) continue;
                #pragma unroll
                for (int dc = 0; dc < 2; dc++) {
                    int cg = cA + dc;
                    float vv = acc[mi][ni][hrow*2 + dc] + bias[cg];
                    if (cg < C_) {
                        __nv_bfloat16 hi = __float2bfloat16(vv);
                        qh[(size_t)r*C_ + cg] = hi;
                        ql[(size_t)r*C_ + cg] = __float2bfloat16(vv - __bfloat162float(hi));
                    } else if (cg < 2*C_) {
                        __nv_bfloat16 hi = __float2bfloat16(vv);
                        kh[(size_t)r*C_ + cg - C_] = hi;
                        kl[(size_t)r*C_ + cg - C_] = __float2bfloat16(vv - __bfloat162float(hi));
                    } else {
                        v[(size_t)r*C_ + cg - 2*C_] = vv;
                    }
                }
            }
        }
    }
}

// --------------------- attention: S = scale*Q@K^T + mask (MMA) ------------------
__global__ __launch_bounds__(MM_THREADS,2) void qk_mma(
    const __nv_bfloat16* __restrict__ qh, const __nv_bfloat16* __restrict__ ql,
    const __nv_bfloat16* __restrict__ kh, const __nv_bfloat16* __restrict__ kl,
    const float* __restrict__ mask, float* __restrict__ S)
{
    extern __shared__ __align__(16) char sm[];
    const int tid = threadIdx.x;
    const int wid = tid >> 5, lane = tid & 31;
    const int wm = wid & 3, wn = wid >> 2;
    const int bh = blockIdx.z, b = bh >> 4, h = bh & 15;
    const int n0 = blockIdx.x * 128, r0 = blockIdx.y * 128;
    const uint32_t smb = smem_u32(sm);
    const size_t hoff = (size_t)b*N_*C_ + h*D_;

    const int nc = (D_ + KC - 1) / KC;
    float acc[2][8][4] = {};

    const __nv_bfloat16* srcs[4] = {qh + hoff, ql + hoff, kh + hoff, kl + hoff};
    const size_t lds[4] = {C_, C_, C_, C_};
    const int rbase[4] = {r0, r0, n0, n0};
    const int rlim[4]  = {N_, N_, N_, N_};

    mma_load_stage(smb, 0, tid, srcs, lds, rbase, rlim, D_);
    for (int c = 0; c < nc; c++) {
        __syncthreads();
        if (c+1 < nc) mma_load_stage(smb, c+1, tid, srcs, lds, rbase, rlim, D_);
        else          CP_COMMIT();
        CP_WAIT1();
        __syncthreads();
        mma_stage_compute(smb, c & 1, wm, wn, lane, acc);
    }

    #pragma unroll
    for (int mi = 0; mi < 2; mi++) {
        int rA = r0 + wm*32 + mi*16 + (lane >> 2);
        #pragma unroll
        for (int ni = 0; ni < 8; ni++) {
            int cA = n0 + wn*64 + ni*8 + (lane & 3)*2;
            #pragma unroll
            for (int hrow = 0; hrow < 2; hrow++) {
                int r = rA + hrow*8;
                if (r >= N_) continue;
                #pragma unroll
                for (int dc = 0; dc < 2; dc++) {
                    int cg = cA + dc;
                    if (cg >= N_) continue;
                    S[((size_t)bh*N_ + r)*NP + cg] =
                        acc[mi][ni][hrow*2 + dc]*SCALE_ + mask[((size_t)b*N_ + r)*N_ + cg];
                }
            }
        }
    }
}

// --------------------- attention: out = P @ V^T (MMA) ---------------------------
__global__ __launch_bounds__(MM_THREADS,2) void av_mma(
    const __nv_bfloat16* __restrict__ ph, const __nv_bfloat16* __restrict__ pl,
    const __nv_bfloat16* __restrict__ vth, const __nv_bfloat16* __restrict__ vtl,
    __nv_bfloat16* __restrict__ outh, __nv_bfloat16* __restrict__ outl)
{
    extern __shared__ __align__(16) char sm[];
    const int tid = threadIdx.x;
    const int wid = tid >> 5, lane = tid & 31;
    const int wm = wid & 3, wn = wid >> 2;
    const int bh = blockIdx.z, b = bh >> 4, h = bh & 15;
    const int r0 = blockIdx.y * 128;
    const uint32_t smb = smem_u32(sm);

    const int nc = NP / KC;
    float acc[2][8][4] = {};

    const __nv_bfloat16* srcs[4] = {
        ph + (size_t)bh*N_*NP, pl + (size_t)bh*N_*NP,
        vth + (size_t)bh*D_*NPV, vtl + (size_t)bh*D_*NPV };
    const size_t lds[4] = {NP, NP, NPV, NPV};
    const int rbase[4] = {r0, r0, 0, 0};
    const int rlim[4]  = {N_, N_, D_, D_};

    mma_load_stage(smb, 0, tid, srcs, lds, rbase, rlim, NP);
    for (int c = 0; c < nc; c++) {
        __syncthreads();
        if (c+1 < nc) mma_load_stage(smb, c+1, tid, srcs, lds, rbase, rlim, NP);
        else          CP_COMMIT();
        CP_WAIT1();
        __syncthreads();
        mma_stage_compute(smb, c & 1, wm, wn, lane, acc);
    }

    #pragma unroll
    for (int mi = 0; mi < 2; mi++) {
        int rA = r0 + wm*32 + mi*16 + (lane >> 2);
        #pragma unroll
        for (int ni = 0; ni < 8; ni++) {
            int cA = wn*64 + ni*8 + (lane & 3)*2;
            #pragma unroll
            for (int hrow = 0; hrow < 2; hrow++) {
                int r = rA + hrow*8;
                if (r >= N_) continue;
                #pragma unroll
                for (int dc = 0; dc < 2; dc++) {
                    int cg = cA + dc;
                    if (cg >= D_) continue;
                    size_t oi = ((size_t)(b*N_ + r))*C_ + h*D_ + cg;
                    float vv = acc[mi][ni][hrow*2 + dc];
                    __nv_bfloat16 hi = __float2bfloat16(vv);
                    outh[oi] = hi;
                    outl[oi] = __float2bfloat16(vv - __bfloat162float(hi));
                }
            }
        }
    }
}

// ----------------------- V transpose + split -----------------------------------
__global__ void vt_kernel(const float* __restrict__ v,
                          __nv_bfloat16* __restrict__ vth, __nv_bfloat16* __restrict__ vtl)
{
    __shared__ float ts[64][D_+1];
    const int bh = blockIdx.y, b = bh >> 4, h = bh & 15;
    const int tt = blockIdx.x;
    for (int i = threadIdx.x; i < 64*D_; i += 256) {
        int tok = i / D_, d = i % D_;
        int n = tt*64 + tok;
        ts[tok][d] = (n < N_) ? v[((size_t)(b*N_ + n))*C_ + h*D_ + d] : 0.f;
    }
    __syncthreads();
    for (int i = threadIdx.x; i < D_*64; i += 256) {
        int d = i / 64, tok = i % 64;
        int n = tt*64 + tok;
        if (n < NPV) {
            float vv = ts[tok][d];
            __nv_bfloat16 hi = __float2bfloat16(vv);
            size_t oi = ((size_t)bh*D_ + d)*NPV + n;
            vth[oi] = hi;
            vtl[oi] = __float2bfloat16(vv - __bfloat162float(hi));
        }
    }
}

// ------------------------------ weight splits ----------------------------------
__global__ void tsplit_qkv_kernel(const float* __restrict__ Wq, const float* __restrict__ Wk,
                                  const float* __restrict__ Wv,
                                  __nv_bfloat16* __restrict__ Th, __nv_bfloat16* __restrict__ Tl)
{
    int i = blockIdx.x*256 + threadIdx.x;
    if (i >= 3*C_*C_) return;
    int which = i / (C_*C_);
    int j = i - which*(C_*C_);
    int n = j / C_, kk = j % C_;
    const float* W = (which == 0) ? Wq : (which == 1) ? Wk : Wv;
    float x = W[(size_t)kk*C_ + n];
    __nv_bfloat16 hi = __float2bfloat16(x);
    Th[i] = hi;
    Tl[i] = __float2bfloat16(x - __bfloat162float(hi));
}

__global__ void tsplit_kernel(const float* __restrict__ W,
                              __nv_bfloat16* __restrict__ Th, __nv_bfloat16* __restrict__ Tl,
                              int K, int Nn)
{
    int i = blockIdx.x*256 + threadIdx.x;
    if (i >= Nn*K) return;
    int n = i / K, kk = i % K;
    float x = W[(size_t)kk*Nn + n];
    __nv_bfloat16 hi = __float2bfloat16(x);
    Th[i] = hi;
    Tl[i] = __float2bfloat16(x - __bfloat162float(hi));
}

__global__ void bconcat_kernel(const float* __restrict__ bq, const float* __restrict__ bk,
                               const float* __restrict__ bv, float* __restrict__ bqkv)
{
    int i = blockIdx.x*256 + threadIdx.x;
    if (i >= 3*C_) return;
    bqkv[i] = (i < C_) ? bq[i] : (i < 2*C_) ? bk[i - C_] : bv[i - 2*C_];
}

// ------------------------------- LayerNorm (+ split) --------------------------
__global__ void ln_kernel(const float* __restrict__ x, const float* __restrict__ g,
                          const float* __restrict__ bb, float* __restrict__ y,
                          __nv_bfloat16* __restrict__ yh, __nv_bfloat16* __restrict__ yl,
                          int cols)
{
    int row = blockIdx.x;
    const float* xr = x + (size_t)row * cols;
    float* yr = y + (size_t)row * cols;
    __shared__ float rs[256], rs2[256];
    float s = 0.f, s2 = 0.f;
    for (int c = threadIdx.x; c < cols; c += 256) { float v = xr[c]; s += v; s2 += v*v; }
    rs[threadIdx.x] = s; rs2[threadIdx.x] = s2; __syncthreads();
    for (int o = 128; o > 0; o >>= 1) {
        if (threadIdx.x < o) { rs[threadIdx.x] += rs[threadIdx.x+o]; rs2[threadIdx.x] += rs2[threadIdx.x+o]; }
        __syncthreads();
    }
    float mean = rs[0] / cols;
    float var  = rs2[0] / cols - mean*mean;
    float rstd = rsqrtf(var + EPSLN);
    for (int c = threadIdx.x; c < cols; c += 256) {
        float v = (xr[c]-mean)*rstd*g[c] + bb[c];
        yr[c] = v;
        if (yh) {
            __nv_bfloat16 hi = __float2bfloat16(v);
            yh[(size_t)row*cols + c] = hi;
            yl[(size_t)row*cols + c] = __float2bfloat16(v - __bfloat162float(hi));
        }
    }
}

// ----------------- metric pipeline (df64 compensated fp32) --------------------
__global__ void wkbar_kernel(const float* __restrict__ wk, float2* __restrict__ wk2)
{
    int idx = blockIdx.x*256 + threadIdx.x;
    if (idx >= C_*D_) return;
    int c = idx / D_, d = idx % D_;
    double s = 0.0;
    #pragma unroll
    for (int hh = 0; hh < H_; hh++) s += (double)wk[(size_t)c*C_ + hh*D_ + d];
    s *= (1.0/H_);
    float hi = (float)s;
    wk2[idx] = make_float2(hi, (float)(s - (double)hi));
}

// K-split metric GEMM: part p handles k in [p*384, (p+1)*384)
#define MT 64
__global__ __launch_bounds__(256) void metricgemm_kernel(
    const float* __restrict__ xln, const float2* __restrict__ wk2,
    double* __restrict__ rawP, int Mtok)
{
    __shared__ float  As[16][MT+1];
    __shared__ float2 Bs[16][D_];
    const int t0 = blockIdx.x * MT;
    const int part = blockIdx.y;
    const int kbeg = part * (C_/3), kend = kbeg + (C_/3);
    const int tl = threadIdx.x & 63, grp = threadIdx.x >> 6;
    float shi[18] = {}, slo[18] = {};
    for (int k0 = kbeg; k0 < kend; k0 += 16) {
        for (int i = threadIdx.x; i < MT*16; i += 256) {
            int kk = i & 15, tok = i >> 4;
            As[kk][tok] = (t0 + tok < Mtok) ? xln[(size_t)(t0+tok)*C_ + k0 + kk] : 0.f;
        }
        for (int i = threadIdx.x; i < 16*D_; i += 256) {
            int kk = i / D_, d = i % D_;
            Bs[kk][d] = wk2[(size_t)(k0+kk)*D_ + d];
        }
        __syncthreads();
        #pragma unroll
        for (int kk = 0; kk < 16; kk++) {
            float a = As[kk][tl];
            #pragma unroll
            for (int j = 0; j < 18; j++) {
                float2 bv = Bs[kk][grp*18 + j];
                df_acc(shi[j], slo[j], a, bv.x, bv.y);
            }
        }
        __syncthreads();
    }
    if (t0 + tl < Mtok) {
        #pragma unroll
        for (int j = 0; j < 18; j++)
            rawP[((size_t)part*Mtok + t0+tl)*D_ + grp*18 + j] = (double)shi[j] + (double)slo[j];
    }
}

__global__ void norm_kernel(const double* __restrict__ rawP, double* __restrict__ mn,
                            const float* __restrict__ bk, int Mtok)
{
    int bn = blockIdx.x;
    __shared__ double val[D_];
    __shared__ double red[128];
    double v = 0.0;
    if (threadIdx.x < D_) {
        double bmean = 0.0;
        #pragma unroll
        for (int hh = 0; hh < H_; hh++) bmean += (double)bk[hh*D_ + threadIdx.x];
        v = rawP[(size_t)bn*D_ + threadIdx.x]
          + rawP[((size_t)Mtok + bn)*D_ + threadIdx.x]
          + rawP[((size_t)2*Mtok + bn)*D_ + threadIdx.x]
          + bmean*(1.0/H_);
        val[threadIdx.x] = v;
    }
    red[threadIdx.x] = v*v; __syncthreads();
    for (int o = 64; o > 0; o >>= 1) {
        if (threadIdx.x < o) red[threadIdx.x] += red[threadIdx.x+o];
        __syncthreads();
    }
    double inv = 1.0 / sqrt(red[0]);
    if (threadIdx.x < D_) mn[(size_t)bn*D_ + threadIdx.x] = val[threadIdx.x]*inv;
}

// ----------------------- softmax: S -> split bf16 P ----------------------------
__global__ __launch_bounds__(256) void softmax_kernel(
    const float* __restrict__ S,
    __nv_bfloat16* __restrict__ ph, __nv_bfloat16* __restrict__ pl)
{
    const float* row = S + (size_t)blockIdx.x * NP;
    size_t base = (size_t)blockIdx.x * NP;
    __shared__ float red[256];
    float ev[3];
    float mx = -1e30f;
    #pragma unroll
    for (int it = 0; it < 3; it++) {
        int j = threadIdx.x + it*256;
        float v = (j < N_) ? row[j] : -1e30f;
        ev[it] = v;
        mx = fmaxf(mx, v);
    }
    red[threadIdx.x] = mx; __syncthreads();
    for (int o = 128; o > 0; o >>= 1) {
        if (threadIdx.x < o) red[threadIdx.x] = fmaxf(red[threadIdx.x], red[threadIdx.x+o]);
        __syncthreads();
    }
    mx = red[0]; __syncthreads();
    float sum = 0.f;
    #pragma unroll
    for (int it = 0; it < 3; it++) {
        int j = threadIdx.x + it*256;
        if (j < N_) { float e = __expf(ev[it] - mx); ev[it] = e; sum += e; }
    }
    red[threadIdx.x] = sum; __syncthreads();
    for (int o = 128; o > 0; o >>= 1) {
        if (threadIdx.x < o) red[threadIdx.x] += red[threadIdx.x+o];
        __syncthreads();
    }
    float inv = 1.f / red[0];
    #pragma unroll
    for (int it = 0; it < 3; it++) {
        int j = threadIdx.x + it*256;
        if (j < N_) {
            float p = ev[it] * inv;
            __nv_bfloat16 hi = __float2bfloat16(p);
            ph[base + j] = hi;
            pl[base + j] = __float2bfloat16(p - __bfloat162float(hi));
        }
    }
    if (threadIdx.x < NP - N_) {
        ph[base + N_ + threadIdx.x] = __float2bfloat16(0.f);
        pl[base + N_ + threadIdx.x] = __float2bfloat16(0.f);
    }
}

// ------------------------- ToMe: per-a-token best match (df64) ----------------
__global__ void tome_score_kernel(const double* __restrict__ mn,
                                  double* __restrict__ nmax, int* __restrict__ nidx)
{
    int b = blockIdx.y, i = blockIdx.x;
    __shared__ float avh[D_], avl[D_];
    __shared__ double bm[128]; __shared__ int bi[128];
    if (threadIdx.x < D_) {
        double a = mn[((size_t)b*N_ + 2*i)*D_ + threadIdx.x];
        float hh = (float)a;
        avh[threadIdx.x] = hh;
        avl[threadIdx.x] = (float)(a - (double)hh);
    }
    __syncthreads();
    double best = -1e300; int bj = 0x7fffffff;
    for (int j = threadIdx.x; j < NB; j += 128) {
        const double* r = mn + ((size_t)b*N_ + 2*j + 1)*D_;
        float dh = 0.f, dl = 0.f;
        #pragma unroll 8
        for (int d = 0; d < D_; d++) {
            double rv = r[d];
            float rh = (float)rv, rl = (float)(rv - (double)rh);
            float ah = avh[d];
            df_acc(dh, dl, ah, rh, rl);
            dl += avl[d]*rh;
        }
        double dot = (double)dh + (double)dl;
        if (dot > best) { best = dot; bj = j; }
    }
    bm[threadIdx.x] = best; bi[threadIdx.x] = bj; __syncthreads();
    for (int o = 64; o > 0; o >>= 1) {
        if (threadIdx.x < o) {
            double ov = bm[threadIdx.x+o]; int oi = bi[threadIdx.x+o];
            if (ov > bm[threadIdx.x] || (ov == bm[threadIdx.x] && oi < bi[threadIdx.x])) {
                bm[threadIdx.x] = ov; bi[threadIdx.x] = oi;
            }
        }
        __syncthreads();
    }
    if (threadIdx.x == 0) { nmax[(size_t)b*NA + i] = bm[0]; nidx[(size_t)b*NA + i] = bi[0]; }
}

__global__ void rank_kernel(const double* __restrict__ nmax, int* __restrict__ edge)
{
    int b = blockIdx.x;
    __shared__ double nm[NA];
    if (threadIdx.x < NA) nm[threadIdx.x] = nmax[(size_t)b*NA + threadIdx.x];
    __syncthreads();
    if (threadIdx.x < NA) {
        double mi = nm[threadIdx.x]; int cnt = 0;
        for (int j = 0; j < NA; j++)
            cnt += (nm[j] > mi) || (nm[j] == mi && j < (int)threadIdx.x);
        edge[(size_t)b*NA + cnt] = threadIdx.x;
    }
}

// ----------------- ToMe merge + LN2 + split (fused) ----------------------------
__global__ void merge_ln_kernel(const float* __restrict__ h, const int* __restrict__ edge,
                                const int* __restrict__ nidx,
                                const float* __restrict__ g, const float* __restrict__ bb,
                                float* __restrict__ mg,
                                __nv_bfloat16* __restrict__ yh, __nv_bfloat16* __restrict__ yl)
{
    int b = blockIdx.y, pos = blockIdx.x;
    __shared__ int ssrc[R_], sdst[R_];
    __shared__ float rowv[C_];
    __shared__ float rs[256], rs2[256];
    if (threadIdx.x < R_) {
        int i = edge[(size_t)b*NA + threadIdx.x];
        ssrc[threadIdx.x] = i;
        sdst[threadIdx.x] = nidx[(size_t)b*NA + i];
    }
    __syncthreads();
    float* mrow = mg + ((size_t)b*NM + pos)*C_;
    if (pos < NU) {
        int i = edge[(size_t)b*NA + R_ + pos];
        const float* sr = h + ((size_t)b*N_ + 2*i)*C_;
        for (int c = threadIdx.x; c < C_; c += 256) rowv[c] = sr[c];
    } else {
        int j = pos - NU;
        const float* dr = h + ((size_t)b*N_ + 2*j + 1)*C_;
        int cnt = 1;
        #pragma unroll
        for (int s = 0; s < R_; s++) cnt += (sdst[s] == j);
        float invc = 1.f / (float)cnt;
        for (int c = threadIdx.x; c < C_; c += 256) {
            float vv = dr[c];
            #pragma unroll
            for (int s = 0; s < R_; s++)
                if (sdst[s] == j) vv += h[((size_t)b*N_ + 2*ssrc[s])*C_ + c];
            rowv[c] = vv*invc;
        }
    }
    __syncthreads();
    float s = 0.f, s2 = 0.f;
    for (int c = threadIdx.x; c < C_; c += 256) { float v = rowv[c]; s += v; s2 += v*v; }
    rs[threadIdx.x] = s; rs2[threadIdx.x] = s2; __syncthreads();
    for (int o = 128; o > 0; o >>= 1) {
        if (threadIdx.x < o) { rs[threadIdx.x] += rs[threadIdx.x+o]; rs2[threadIdx.x] += rs2[threadIdx.x+o]; }
        __syncthreads();
    }
    float mean = rs[0] / C_;
    float var  = rs2[0] / C_ - mean*mean;
    float rstd = rsqrtf(var + EPSLN);
    size_t base = ((size_t)b*NM + pos)*C_;
    for (int c = threadIdx.x; c < C_; c += 256) {
        float raw = rowv[c];
        mrow[c] = raw;
        float v = (raw-mean)*rstd*g[c] + bb[c];
        __nv_bfloat16 hi = __float2bfloat16(v);
        yh[base + c] = hi;
        yl[base + c] = __float2bfloat16(v - __bfloat162float(hi));
    }
}

// --------------------------------- driver -------------------------------------
extern "C" void kernel_launch(void* const* d_in, const int* in_sizes, int n_in,
                              void* d_out, int out_size)
{
    const float* hs   = (const float*)d_in[0];
    const float* mask = (const float*)d_in[1];
    const float* wq   = (const float*)d_in[2];
    const float* bq   = (const float*)d_in[3];
    const float* wk   = (const float*)d_in[4];
    const float* bk   = (const float*)d_in[5];
    const float* wv   = (const float*)d_in[6];
    const float* bv   = (const float*)d_in[7];
    const float* wo   = (const float*)d_in[8];
    const float* bo   = (const float*)d_in[9];
    const float* ln1w = (const float*)d_in[10];
    const float* ln1b = (const float*)d_in[11];
    const float* ln2w = (const float*)d_in[12];
    const float* ln2b = (const float*)d_in[13];
    const float* fc1w = (const float*)d_in[14];
    const float* fc1b = (const float*)d_in[15];
    const float* fc2w = (const float*)d_in[16];
    const float* fc2b = (const float*)d_in[17];

    float *xln, *v, *h, *sc, *mg, *bqkv;
    float2 *wk2;
    double *mnP, *mnD, *nmax;
    int *nidx, *edge;
    __nv_bfloat16 *xh,*xl,*qh,*ql,*kh,*kl,*ph,*pl,*vth,*vtl,*aoh,*aol,*h2h,*h2l,*f1h,*f1l;
    __nv_bfloat16 *wqkvth,*wqkvtl,*woth,*wotl,*w1th,*w1tl,*w2th,*w2tl;
    cudaGetSymbolAddress((void**)&xln,   g_xln);
    cudaGetSymbolAddress((void**)&v,     g_v);
    cudaGetSymbolAddress((void**)&h,     g_h);
    cudaGetSymbolAddress((void**)&sc,    g_sc);
    cudaGetSymbolAddress((void**)&wk2,   g_wk2);
    cudaGetSymbolAddress((void**)&mnP,   g_mnP);
    cudaGetSymbolAddress((void**)&mnD,   g_mnD);
    cudaGetSymbolAddress((void**)&nmax,  g_nmax);
    cudaGetSymbolAddress((void**)&nidx,  g_nidx);
    cudaGetSymbolAddress((void**)&edge,  g_edge);
    cudaGetSymbolAddress((void**)&mg,    g_mg);
    cudaGetSymbolAddress((void**)&bqkv,  g_bqkv);
    cudaGetSymbolAddress((void**)&xh,    g_xh);
    cudaGetSymbolAddress((void**)&xl,    g_xl);
    cudaGetSymbolAddress((void**)&qh,    g_qh);
    cudaGetSymbolAddress((void**)&ql,    g_ql);
    cudaGetSymbolAddress((void**)&kh,    g_kh);
    cudaGetSymbolAddress((void**)&kl,    g_kl);
    cudaGetSymbolAddress((void**)&ph,    g_ph);
    cudaGetSymbolAddress((void**)&pl,    g_pl);
    cudaGetSymbolAddress((void**)&vth,   g_vth);
    cudaGetSymbolAddress((void**)&vtl,   g_vtl);
    cudaGetSymbolAddress((void**)&aoh,   g_aoh);
    cudaGetSymbolAddress((void**)&aol,   g_aol);
    cudaGetSymbolAddress((void**)&h2h,   g_h2h);
    cudaGetSymbolAddress((void**)&h2l,   g_h2l);
    cudaGetSymbolAddress((void**)&f1h,   g_f1h);
    cudaGetSymbolAddress((void**)&f1l,   g_f1l);
    cudaGetSymbolAddress((void**)&wqkvth, g_wqkvth);
    cudaGetSymbolAddress((void**)&wqkvtl, g_wqkvtl);
    cudaGetSymbolAddress((void**)&woth,  g_woth);
    cudaGetSymbolAddress((void**)&wotl,  g_wotl);
    cudaGetSymbolAddress((void**)&w1th,  g_w1th);
    cudaGetSymbolAddress((void**)&w1tl,  g_w1tl);
    cudaGetSymbolAddress((void**)&w2th,  g_w2th);
    cudaGetSymbolAddress((void**)&w2tl,  g_w2tl);

    cudaFuncSetAttribute(mma_gemm,     cudaFuncAttributeMaxDynamicSharedMemorySize, MM_SMEM);
    cudaFuncSetAttribute(mma_gemm_qkv, cudaFuncAttributeMaxDynamicSharedMemorySize, MM_SMEM);
    cudaFuncSetAttribute(qk_mma,       cudaFuncAttributeMaxDynamicSharedMemorySize, MM_SMEM);
    cudaFuncSetAttribute(av_mma,       cudaFuncAttributeMaxDynamicSharedMemorySize, MM_SMEM);

    const int MN1 = B_*N_;    // 5832
    const int MN2 = B_*NM;    // 5648
    const int GY1 = (MN1+127)/128;
    const int GY2 = (MN2+127)/128;
    const int QT  = (N_+127)/128;

    // launches 1-3: combined qkv weight split, bias concat, LN1
    tsplit_qkv_kernel<<<(3*C_*C_+255)/256, 256>>>(wq, wk, wv, wqkvth, wqkvtl);
    bconcat_kernel<<<(3*C_+255)/256, 256>>>(bq, bk, bv, bqkv);
    ln_kernel<<<MN1, 256>>>(hs, ln1w, ln1b, xln, xh, xl, C_);

    // launch 4: fused QKV (profiled launch)
    mma_gemm_qkv<<<dim3(3*C_/128, GY1), MM_THREADS, MM_SMEM>>>(xh, xl, wqkvth, wqkvtl, bqkv,
                                                               qh, ql, kh, kl, v, MN1);

    // metric pipeline (K-split x3)
    wkbar_kernel<<<(C_*D_+255)/256, 256>>>(wk, wk2);
    metricgemm_kernel<<<dim3((MN1+MT-1)/MT, 3), 256>>>(xln, wk2, mnP, MN1);
    norm_kernel<<<MN1, 128>>>(mnP, mnD, bk, MN1);

    // attention
    vt_kernel<<<dim3((NPV+63)/64, B_*H_), 256>>>(v, vth, vtl);
    qk_mma<<<dim3(QT, QT, B_*H_), MM_THREADS, MM_SMEM>>>(qh, ql, kh, kl, mask, sc);
    softmax_kernel<<<B_*H_*N_, 256>>>(sc, ph, pl);
    av_mma<<<dim3(1, QT, B_*H_), MM_THREADS, MM_SMEM>>>(ph, pl, vth, vtl, aoh, aol);

    // output projection + residual
    tsplit_kernel<<<(C_*C_+255)/256, 256>>>(wo, woth, wotl, C_, C_);
    mma_gemm<<<dim3(C_/128, GY1), MM_THREADS, MM_SMEM>>>(aoh, aol, woth, wotl, bo, hs, h, nullptr, nullptr, MN1, C_, C_, 0);

    // ToMe + fused merge/LN2/split
    tome_score_kernel<<<dim3(NA, B_), 128>>>(mnD, nmax, nidx);
    rank_kernel<<<B_, 512>>>(nmax, edge);
    merge_ln_kernel<<<dim3(NM, B_), 256>>>(h, edge, nidx, ln2w, ln2b, mg, h2h, h2l);

    // MLP
    tsplit_kernel<<<(F_*C_+255)/256, 256>>>(fc1w, w1th, w1tl, C_, F_);
    tsplit_kernel<<<(F_*C_+255)/256, 256>>>(fc2w, w2th, w2tl, F_, C_);
    mma_gemm<<<dim3((F_+127)/128, GY2), MM_THREADS, MM_SMEM>>>(h2h, h2l, w1th, w1tl, fc1b, nullptr, nullptr, f1h, f1l, MN2, F_, C_, 1);
    mma_gemm<<<dim3(C_/128, GY2), MM_THREADS, MM_SMEM>>>(f1h, f1l, w2th, w2tl, fc2b, mg, (float*)d_out, nullptr, nullptr, MN2, C_, F_, 0);
}